// round 16
// baseline (speedup 1.0000x reference)
#include <cuda_runtime.h>

// SparseMCFModel — math reduction (validated over 14 passing rounds):
//  * decoder softmax has identical logits within each segment
//    => w[e] = 1/out_degree(edge_row[e]) EXACTLY. GAT/GRU/decoder dead code.
//  * recurrence: x_1 = relu(demands);
//      x_{t+1}[n] = dpos[n] + sum_{e: col(e)=n} w[e]*x_t[row(e)]
//      flow[e]    = w[e] * x_10[row(e)]
//
// R9..R15: PDL multi-launch plateaus at 41us — ~2us/boundary x 10 is
// structural. This round: ONE cooperative persistent kernel at the proven
// full-machine shape (782 blocks x 256, 1 edge/thread in registers) with a
// cheap tree barrier. Prior persistent failures were confounded (R2: atomic
// polling; R3/R5: 25% occupancy). Barrier: 32 padded arrival counters,
// MONOTONE across replays (no resets -> no reset/poll races; blocks read the
// base generation at entry, provably before barrier 1 can release), volatile
// poll on g_gen, per-thread __threadfence publishes REDs, __ldcg for all
// cross-block gathers (L1 bypass). PDL multi-launch kept as fallback.

#define NN   20000
#define NE   200000
#define BS   256
#define GEC  782          // coop grid: 782*256 = 200192 >= NE (1 edge/thread)
#define NBAR 10
#define NCNT 32

__device__ float d_dpos[NN];
__device__ float d_x[3][NN];
__device__ int   d_deg[NN];   // zero at replay start (static init / epilogue rezero)

// ---- monotone tree barrier state (never reset; targets are absolute) ----
struct alignas(128) Slot { unsigned int v; unsigned int pad[31]; };
__device__ Slot                  g_cnt[NCNT];
__device__ unsigned int          g_done = 0;
__device__ volatile unsigned int g_gen  = 0;

__device__ __forceinline__ void gsync(unsigned int nb, unsigned int A) {
    // A = absolute (cross-replay) barrier index, 1-based; valid in thread 0 only.
    __threadfence();                 // every thread publishes its REDs/stores
    __syncthreads();
    if (threadIdx.x == 0) {
        unsigned int j    = blockIdx.x & (NCNT - 1);
        unsigned int expj = (nb + NCNT - 1 - j) / NCNT;   // #blocks with bid%32==j
        unsigned int a = atomicAdd(&g_cnt[j].v, 1u) + 1u;
        if (a == expj * A) {                              // last arriver on slot j, gen A
            unsigned int d = atomicAdd(&g_done, 1u) + 1u;
            if (d == NCNT * A) {                          // last slot done => release
                __threadfence();
                g_gen = A;
            }
        }
        while (g_gen < A) __nanosleep(32);
        __threadfence();             // acquire
    }
    __syncthreads();
}

// ---------------- persistent cooperative solver ----------------
__global__ void __launch_bounds__(BS, 6)
k_solve(const float* __restrict__ demands, const int* __restrict__ row,
        const int* __restrict__ col, float* __restrict__ out) {
    const unsigned int nb = gridDim.x;
    const int tid = blockIdx.x * BS + threadIdx.x;
    const int T   = (int)nb * BS;

    // Base generation: every block reads BEFORE its own barrier-1 arrival, and
    // barrier 1 cannot release until all blocks arrive => uniform G0 = R*NBAR.
    unsigned int G0 = 0;
    if (threadIdx.x == 0) G0 = g_gen;

    const bool ve = (tid < NE);
    int r = 0, c = 0;
    if (ve) { r = __ldg(&row[tid]); c = __ldg(&col[tid]); }

    // prologue: node init + degree histogram (deg is zero at entry)
    for (int i = tid; i < NN; i += T) {
        float d = __ldg(&demands[i]);
        d = d > 0.0f ? d : 0.0f;
        d_dpos[i] = d;
        d_x[0][i] = d;                // x_1
        d_x[1][i] = d;                // iter-1 write target, pre-reset
    }
    if (ve) atomicAdd(&d_deg[r], 1);
    gsync(nb, G0 + 1);

    // weights + iter 1 (x_1 -> x_2) + reset of iter-2's target
    float w = 0.0f;
    if (ve) {
        w = 1.0f / (float)__ldcg(&d_deg[r]);
        atomicAdd(&d_x[1][c], w * __ldcg(&d_x[0][r]));
    }
    for (int i = tid; i < NN; i += T) d_x[2][i] = d_dpos[i];
    gsync(nb, G0 + 2);

    // iters 2..9: read x[(t-1)%3], RED into x[t%3], reset x[(t+1)%3]
#pragma unroll 1
    for (int t = 2; t <= 9; t++) {
        int cur = (t - 1) % 3, nxt = t % 3, rst = (t + 1) % 3;
        if (ve) {
            float xv = __ldcg(&d_x[cur][r]);          // L1-bypass gather
            atomicAdd(&d_x[nxt][c], w * xv);          // fire-and-forget RED
        }
        if (t < 9)
            for (int i = tid; i < NN; i += T) d_x[rst][i] = d_dpos[i];
        gsync(nb, G0 + 1 + t);        // barriers 3..10
    }

    // epilogue (after barrier 10): x_10 lives in d_x[9%3] = d_x[0]
    if (ve) out[tid] = w * __ldcg(&d_x[0][r]);
    for (int i = tid; i < NN; i += T) d_deg[i] = 0;   // rezero for next replay
}

// ---------------- fallback: proven PDL multi-launch path (41.0us) ----------------
#define GE ((NE + BS - 1) / BS)

__device__ float f_w[NE];
__device__ float f_x[4][NN];

__device__ __forceinline__ void pdl_trigger() {
    asm volatile("griddepcontrol.launch_dependents;" ::: "memory");
}
__device__ __forceinline__ void pdl_wait() {
    asm volatile("griddepcontrol.wait;" ::: "memory");
}

__global__ void __launch_bounds__(BS) f_init_deg(const float* __restrict__ demands,
                                                 const int* __restrict__ row) {
    int i = blockIdx.x * BS + threadIdx.x;
    pdl_trigger();
    if (i < NN / 2) {
        float2 d = __ldg((const float2*)demands + i);
        d.x = d.x > 0.0f ? d.x : 0.0f;
        d.y = d.y > 0.0f ? d.y : 0.0f;
        ((float2*)d_dpos)[i] = d;
        ((float2*)f_x[0])[i] = d;
        ((float2*)f_x[1])[i] = d;
        ((float2*)f_x[2])[i] = d;
    }
    if (i < NE) atomicAdd(&d_deg[__ldg(&row[i])], 1);
}
__global__ void __launch_bounds__(BS) f_upd_first(const int* __restrict__ row,
                                                  const int* __restrict__ col) {
    int i = blockIdx.x * BS + threadIdx.x;
    int r = 0, c = 0;
    if (i < NE) { r = __ldg(&row[i]); c = __ldg(&col[i]); }
    pdl_wait();
    pdl_trigger();
    if (i < NE) {
        float w = 1.0f / (float)d_deg[r];
        f_w[i] = w;
        atomicAdd(&f_x[1][c], w * f_x[0][r]);
    }
}
__global__ void __launch_bounds__(BS) f_upd2(const int* __restrict__ row,
                                             const int* __restrict__ col) {
    int i = blockIdx.x * BS + threadIdx.x;
    int r = 0, c = 0;
    if (i < NE) { r = __ldg(&row[i]); c = __ldg(&col[i]); }
    if (i < NN / 2) ((float2*)f_x[3])[i] = ((const float2*)d_dpos)[i];
    pdl_wait();
    pdl_trigger();
    if (i < NE) atomicAdd(&f_x[2][c], f_w[i] * __ldg(&f_x[1][r]));
}
__global__ void __launch_bounds__(BS) f_update(const int* __restrict__ row,
                                               const int* __restrict__ col,
                                               int cur, int nxt, int rst) {
    int i = blockIdx.x * BS + threadIdx.x;
    int r = 0, c = 0;
    float w = 0.0f;
    if (i < NE) { r = __ldg(&row[i]); c = __ldg(&col[i]); w = f_w[i]; }
    if (i < NN / 2) ((float2*)f_x[rst])[i] = ((const float2*)d_dpos)[i];
    pdl_wait();
    pdl_trigger();
    if (i < NE) atomicAdd(&f_x[nxt][c], w * __ldg(&f_x[cur][r]));
}
__global__ void __launch_bounds__(BS) f_final(const int* __restrict__ row,
                                              float* __restrict__ out, int cur) {
    int e = blockIdx.x * BS + threadIdx.x;
    int r = 0; float w = 0.0f;
    if (e < NE) { r = __ldg(&row[e]); w = f_w[e]; }
    if (e < NN) d_deg[e] = 0;
    pdl_wait();
    if (e < NE) out[e] = w * __ldg(&f_x[cur][r]);
}

static inline void launch_pdl(const void* fn, void** args) {
    cudaLaunchConfig_t cfg = {};
    cfg.gridDim  = dim3(GE);
    cfg.blockDim = dim3(BS);
    cfg.stream = 0;
    cudaLaunchAttribute at;
    at.id = cudaLaunchAttributeProgrammaticStreamSerialization;
    at.val.programmaticStreamSerializationAllowed = 1;
    cfg.attrs = &at;
    cfg.numAttrs = 1;
    if (cudaLaunchKernelExC(&cfg, fn, args) != cudaSuccess) {
        cudaGetLastError();
        cfg.numAttrs = 0;
        cudaLaunchKernelExC(&cfg, fn, args);
    }
}

static void run_fallback(const float* demands, const int* erow, const int* ecol,
                         float* out) {
    f_init_deg<<<GE, BS>>>(demands, erow);
    { void* a[2] = { (void*)&erow, (void*)&ecol }; launch_pdl((const void*)f_upd_first, a); }
    { void* a[2] = { (void*)&erow, (void*)&ecol }; launch_pdl((const void*)f_upd2, a); }
    for (int t = 3; t <= 9; t++) {
        int cur = (t - 1) & 3, nxt = t & 3, rst = (t + 1) & 3;
        void* a[5] = { (void*)&erow, (void*)&ecol, &cur, &nxt, &rst };
        launch_pdl((const void*)f_update, a);
    }
    { int cur = 9 & 3; void* a[3] = { (void*)&erow, (void*)&out, &cur };
      launch_pdl((const void*)f_final, a); }
}

extern "C" void kernel_launch(void* const* d_in, const int* in_sizes, int n_in,
                              void* d_out, int out_size) {
    // Inputs: node_embeddings, demands, edge_row, edge_col, ...
    const float* demands = (const float*)d_in[1];
    const int*   erow    = (const int*)d_in[2];
    const int*   ecol    = (const int*)d_in[3];
    float*       out     = (float*)d_out;

    static int coop_ok = -1;   // -1 = unprobed
    if (coop_ok == -1) {
        int dev = 0, nsm = 0, coop = 0, bpsm = 0;
        cudaGetDevice(&dev);
        cudaDeviceGetAttribute(&nsm,  cudaDevAttrMultiProcessorCount, dev);
        cudaDeviceGetAttribute(&coop, cudaDevAttrCooperativeLaunch,   dev);
        cudaOccupancyMaxActiveBlocksPerMultiprocessor(&bpsm, k_solve, BS, 0);
        coop_ok = (coop && (long long)nsm * bpsm >= GEC && GEC >= NCNT) ? 1 : 0;
    }

    if (coop_ok == 1) {
        void* args[4] = { (void*)&demands, (void*)&erow, (void*)&ecol, (void*)&out };
        cudaError_t err = cudaLaunchCooperativeKernel(
            (void*)k_solve, dim3(GEC), dim3(BS), args, 0, 0);
        if (err == cudaSuccess) return;
        cudaGetLastError();
        coop_ok = 0;
    }

    run_fallback(demands, erow, ecol, out);
}

// round 17
// speedup vs baseline: 1.5157x; 1.5157x over previous
#include <cuda_runtime.h>

// SparseMCFModel — math reduction (validated over 15 passing rounds):
//  * decoder softmax has identical logits within each segment
//    => w[e] = 1/out_degree(edge_row[e]) EXACTLY. GAT/GRU/decoder dead code.
//  * recurrence: x_1 = relu(demands);
//      x_{t+1}[n] = dpos[n] + sum_{e: col(e)=n} w[e]*x_t[row(e)]
//      flow[e]    = w[e] * x_10[row(e)]
//
// FINAL STRUCTURE (plateau established):
//  - PDL-chained 11-node graph, full-wave grids (782 x 256, 1 edge/thread).
//    Persistent/cooperative kernels measured 65-80us across 4 designs
//    (software barriers cost >= HW kernel boundaries); edge sorting measured
//    net-negative; 9 sequential SpMVs are mathematically irreducible.
//  - Safety invariant: pdl_trigger strictly AFTER pdl_wait => max 2
//    generations overlap. 4-buffer rotation: step t reads x[(t-1)%4], writes
//    x[t%4], resets x[(t+1)%4]; concurrent step t-1 touches {t-2,t-1,t}%4 —
//    disjoint. Init writes x[0..2] so step-1's pre-wait is pure-input-only.
//  - NEW: k_init_deg is PDL-gated and k_final triggers post-wait, so across
//    graph REPLAYS the next init's input prefetch overlaps k_final's body.

#define NN 20000
#define NE 200000
#define BS 256
#define GE ((NE + BS - 1) / BS)   // 782 blocks (full wave); covers NN too

__device__ float d_dpos[NN];
__device__ float d_x[4][NN];
__device__ int   d_deg[NN];   // zero at replay start (static init / k_final rezero)
__device__ float d_w[NE];     // per-edge weight (written by k_upd_first only)

__device__ __forceinline__ void pdl_trigger() {
    asm volatile("griddepcontrol.launch_dependents;" ::: "memory");
}
__device__ __forceinline__ void pdl_wait() {
    asm volatile("griddepcontrol.wait;" ::: "memory");
}

// node 1: node-init (x[0..2] = dpos, float2) + degree histogram.
// PDL-gated: pre-wait touches ONLY pure inputs; wait orders all stores after
// the PREVIOUS REPLAY's k_final (which reads d_x[1] and rezeroes d_deg).
__global__ void __launch_bounds__(BS) k_init_deg(const float* __restrict__ demands,
                                                 const int* __restrict__ row) {
    int i = blockIdx.x * BS + threadIdx.x;
    float2 d = make_float2(0.f, 0.f);
    int r = 0;
    if (i < NN / 2) {
        d = __ldg((const float2*)demands + i);
        d.x = d.x > 0.0f ? d.x : 0.0f;
        d.y = d.y > 0.0f ? d.y : 0.0f;
    }
    if (i < NE) r = __ldg(&row[i]);
    pdl_wait();                            // prior replay's k_final done
    pdl_trigger();                         // release k_upd_first's pre-wait
    if (i < NN / 2) {
        ((float2*)d_dpos)[i] = d;
        ((float2*)d_x[0])[i] = d;     // x_1 (read buffer of step 1)
        ((float2*)d_x[1])[i] = d;     // step 1 write target, pre-reset
        ((float2*)d_x[2])[i] = d;     // step 2 write target, pre-reset
    }
    if (i < NE) atomicAdd(&d_deg[r], 1);
}

// node 2 (step 1): x_1 -> x_2 + weight precompute. Pre-wait: pure inputs only.
__global__ void __launch_bounds__(BS) k_upd_first(const int* __restrict__ row,
                                                  const int* __restrict__ col) {
    int i = blockIdx.x * BS + threadIdx.x;
    int r = 0, c = 0;
    if (i < NE) { r = __ldg(&row[i]); c = __ldg(&col[i]); }
    pdl_wait();                            // init + deg complete + visible
    pdl_trigger();                         // release step 2's pre-wait
    if (i < NE) {
        float w = 1.0f / (float)d_deg[r];
        d_w[i] = w;
        atomicAdd(&d_x[1][c], w * d_x[0][r]);   // fire-and-forget RED
    }
}

// node 3 (step 2): specialized — w loaded POST-wait (writer is predecessor).
// Pre-wait: pure inputs + reset x[3] (untouched by step 1: {0,1}).
__global__ void __launch_bounds__(BS) k_upd2(const int* __restrict__ row,
                                             const int* __restrict__ col) {
    int i = blockIdx.x * BS + threadIdx.x;
    int r = 0, c = 0;
    if (i < NE) { r = __ldg(&row[i]); c = __ldg(&col[i]); }
    if (i < NN / 2) ((float2*)d_x[3])[i] = ((const float2*)d_dpos)[i];
    pdl_wait();                            // step 1 complete + visible
    pdl_trigger();
    if (i < NE) {
        float w  = d_w[i];
        float xv = __ldg(&d_x[1][r]);      // ONE random gather
        atomicAdd(&d_x[2][c], w * xv);     // ONE fire-and-forget RED
    }
}

// nodes 4..10 (steps 3..9): generic, w pre-wait (immutable since step 1).
// Pre-wait overlaps only step t-1: resets x[(t+1)%4], disjoint from t-1's
// buffer set {t-2,t-1,t}%4; d_dpos/d_w immutable during overlap window.
__global__ void __launch_bounds__(BS) k_update(const int* __restrict__ row,
                                               const int* __restrict__ col,
                                               int cur, int nxt, int rst) {
    int i = blockIdx.x * BS + threadIdx.x;
    int r = 0, c = 0;
    float w = 0.0f;
    if (i < NE) {
        r = __ldg(&row[i]); c = __ldg(&col[i]);
        w = d_w[i];                        // immutable: safe pre-wait
    }
    if (i < NN / 2) ((float2*)d_x[rst])[i] = ((const float2*)d_dpos)[i];
    pdl_wait();                            // step t-1 complete + visible
    pdl_trigger();
    if (i < NE) {
        float xv = __ldg(&d_x[cur][r]);    // ONE random gather (post-wait)
        atomicAdd(&d_x[nxt][c], w * xv);   // ONE fire-and-forget RED
    }
}

// node 11: flow = w * x_10[row]; rezero d_deg. Triggers POST-wait so the next
// replay's k_init_deg prefetches inputs during this kernel's body; that init's
// stores are gated by its own pdl_wait on THIS kernel.
__global__ void __launch_bounds__(BS) k_final(const int* __restrict__ row,
                                              float* __restrict__ out, int cur) {
    int e = blockIdx.x * BS + threadIdx.x;
    int r = 0; float w = 0.0f;
    if (e < NE) { r = __ldg(&row[e]); w = d_w[e]; }
    pdl_wait();                            // step 9 complete + visible
    pdl_trigger();                         // release next replay's init pre-wait
    if (e < NE) out[e] = w * __ldg(&d_x[cur][r]);
    if (e < NN) d_deg[e] = 0;              // rezero for next replay
}

static inline void launch_pdl(const void* fn, void** args) {
    cudaLaunchConfig_t cfg = {};
    cfg.gridDim  = dim3(GE);
    cfg.blockDim = dim3(BS);
    cfg.dynamicSmemBytes = 0;
    cfg.stream = 0;
    cudaLaunchAttribute at;
    at.id = cudaLaunchAttributeProgrammaticStreamSerialization;
    at.val.programmaticStreamSerializationAllowed = 1;
    cfg.attrs = &at;
    cfg.numAttrs = 1;
    if (cudaLaunchKernelExC(&cfg, fn, args) != cudaSuccess) {
        cudaGetLastError();
        cfg.numAttrs = 0;                  // fallback: serialized launch (wait is benign)
        cudaLaunchKernelExC(&cfg, fn, args);
    }
}

extern "C" void kernel_launch(void* const* d_in, const int* in_sizes, int n_in,
                              void* d_out, int out_size) {
    // Inputs: node_embeddings, demands, edge_row, edge_col, W_gat, a_src,
    //         a_dst, Wx, Wh, b_gru, Wd, bd
    const float* demands = (const float*)d_in[1];
    const int*   erow    = (const int*)d_in[2];
    const int*   ecol    = (const int*)d_in[3];
    float*       out     = (float*)d_out;

    {
        void* args[2] = { (void*)&demands, (void*)&erow };
        launch_pdl((const void*)k_init_deg, args);
    }
    {
        void* args[2] = { (void*)&erow, (void*)&ecol };
        launch_pdl((const void*)k_upd_first, args);
    }
    {
        void* args[2] = { (void*)&erow, (void*)&ecol };
        launch_pdl((const void*)k_upd2, args);
    }

    // steps 3..9: read x[(t-1)%4], write x[t%4], reset x[(t+1)%4]
    for (int t = 3; t <= 9; t++) {
        int cur = (t - 1) & 3, nxt = t & 3, rst = (t + 1) & 3;
        void* args[5] = { (void*)&erow, (void*)&ecol, &cur, &nxt, &rst };
        launch_pdl((const void*)k_update, args);
    }

    {
        int cur = 9 & 3;   // x_10 lives in d_x[1]
        void* args[3] = { (void*)&erow, (void*)&out, &cur };
        launch_pdl((const void*)k_final, args);
    }
}